// round 9
// baseline (speedup 1.0000x reference)
#include <cuda_runtime.h>
#include <cuda_fp16.h>
#include <cstring>

#define NN 100000
#define EE 400000
#define D4 64          // 256 floats = 64 float4 per row
#define SS 10000
#define CAP 64         // bucket capacity per node (Poisson(8): P(>64) ~ 0)

// ---------------- static scratch (no runtime allocation) ----------------
// g_cursor is zero-initialized at module load and re-zeroed at the END of
// each kernel_launch (in k_seed), so every call starts from zeros.
__device__ int    g_cursor[2][NN];            // degree counts (bucket cursors)
__device__ int    g_adj[2][(size_t)NN * CAP]; // bucket adjacency
__device__ float  g_dinv[2][NN];
__device__ uint2  g_h0[2][(size_t)NN * 64];   // fp16 pre-scaled g0 = h*dinv (512B/row)
__device__ uint2  g_h1[2][(size_t)NN * 64];   // fp16 pre-scaled g1

// ---------------- half2 <-> float helpers ----------------
__device__ __forceinline__ float2 u2f(unsigned int u) {
    __half2 h; memcpy(&h, &u, 4); return __half22float2(h);
}
__device__ __forceinline__ unsigned int f2u(float a, float b) {
    __half2 h = __floats2half2_rn(a, b); unsigned int u; memcpy(&u, &h, 4); return u;
}
__device__ __forceinline__ void unpack_add4(float* a, uint2 v) {
    float2 f;
    f = u2f(v.x); a[0] += f.x; a[1] += f.y;
    f = u2f(v.y); a[2] += f.x; a[3] += f.y;
}

// ---------------- bucket fill: one pass builds adjacency AND degrees ------
__global__ void k_fill(const int2* __restrict__ esr, const int2* __restrict__ etg) {
    int i = blockIdx.x * 256 + threadIdx.x;
    if (i >= 2 * EE) return;
    int side = i >= EE;
    int j = i - side * EE;
    int2 ab = side ? etg[j] : esr[j];
    int p = atomicAdd(&g_cursor[side][ab.x], 1);
    if (p < CAP) g_adj[side][(size_t)ab.x * CAP + p] = ab.y;
    int q = atomicAdd(&g_cursor[side][ab.y], 1);
    if (q < CAP) g_adj[side][(size_t)ab.y * CAP + q] = ab.x;
}

// dinv[v] = rsqrt(deg[v] + 1)   (cursor count == degree)
__global__ void k_dinv() {
    int i = blockIdx.x * 256 + threadIdx.x;
    if (i >= 2 * NN) return;
    int side = i >= NN;
    int v = i - side * NN;
    g_dinv[side][v] = rsqrtf((float)(g_cursor[side][v] + 1));
}

// g0 = fp16(feats * dinv[row]); one uint4 (8 halfs) per thread
__global__ void k_conv(const float4* __restrict__ fsr, const float4* __restrict__ ftg) {
    int i = blockIdx.x * 256 + threadIdx.x;
    if (i >= 2 * NN * 32) return;
    int side = i >= NN * 32;
    int j = i - side * NN * 32;
    float s = g_dinv[side][j >> 5];
    const float4* f = side ? ftg : fsr;
    float4 x0 = __ldcs(f + 2 * j);        // streaming: feats never reused
    float4 x1 = __ldcs(f + 2 * j + 1);
    uint4 o;
    o.x = f2u(x0.x * s, x0.y * s);
    o.y = f2u(x0.z * s, x0.w * s);
    o.z = f2u(x1.x * s, x1.y * s);
    o.w = f2u(x1.z * s, x1.w * s);
    ((uint4*)g_h0[side])[j] = o;
}

// ---------------- aggregation: TWO warps per node, 4 floats / lane -------
// Row of 256 floats = 64 uint2; warp half h covers uint2 columns h*32+lane.
// Block = 256 threads = 8 warps = 4 nodes; grid = NN/4 = 25000 (exact).
// Input table pre-scaled by dinv -> inner loop is a pure gather-add.
// FINAL=false: g1[v] = fp16( relu(dinv[v]*acc) * dinv[v] )  -> g_h1
// FINAL=true : row    = l2normalize(dinv[v]*acc)            -> d_out (fp32, stcs)
template <bool FINAL>
__global__ void k_layer(int side, float4* out) {
    int wib  = threadIdx.x >> 5;            // warp in block: 0..7
    int lane = threadIdx.x & 31;
    int nl   = wib >> 1;                    // node slot in block: 0..3
    int half = wib & 1;                     // which half-row this warp owns
    int gw   = blockIdx.x * 4 + nl;         // node id (exact cover of NN)
    int col  = half * 32 + lane;            // uint2 column within the row

    const uint2* __restrict__ gin = FINAL ? g_h1[side] : g_h0[side];
    float a[4] = {0, 0, 0, 0};
    unpack_add4(a, __ldg(gin + (size_t)gw * 64 + col));   // self loop

    int e = min(g_cursor[side][gw], CAP);
    const int* __restrict__ adj = g_adj[side] + (size_t)gw * CAP;
    for (int base = 0; base < e; base += 32) {
        int cnt = min(32, e - base);
        int nb = (lane < cnt) ? __ldg(adj + base + lane) : 0;
        for (int k = 0; k < cnt; k++) {
            int u = __shfl_sync(0xffffffffu, nb, k);
            unpack_add4(a, __ldg(gin + (size_t)u * 64 + col));
        }
    }

    float dv = g_dinv[side][gw];
    if (!FINAL) {
        float r[4];
        #pragma unroll
        for (int k = 0; k < 4; k++) r[k] = fmaxf(dv * a[k], 0.f) * dv;
        uint2 o;
        o.x = f2u(r[0], r[1]); o.y = f2u(r[2], r[3]);
        g_h1[side][(size_t)gw * 64 + col] = o;
    } else {
        __shared__ float s_ss[4][2];
        float r[4];
        float ss = 0.f;
        #pragma unroll
        for (int k = 0; k < 4; k++) { r[k] = dv * a[k]; ss += r[k] * r[k]; }
        #pragma unroll
        for (int off = 16; off; off >>= 1) ss += __shfl_xor_sync(0xffffffffu, ss, off);
        if (lane == 0) s_ss[nl][half] = ss;
        __syncthreads();
        float tot = s_ss[nl][0] + s_ss[nl][1];
        float inv = 1.0f / fmaxf(sqrtf(tot), 1e-12f);
        float4 r4;
        r4.x = r[0] * inv; r4.y = r[1] * inv; r4.z = r[2] * inv; r4.w = r[3] * inv;
        size_t rb = (size_t)(2 * SS) * D4 + (size_t)side * NN * D4 + (size_t)gw * D4;
        __stcs(out + rb + col, r4);            // streaming: keep table in L2
    }
}

// seed gather + re-zero bucket cursors for the next call
__global__ void k_seed(const int* __restrict__ ssr, const int* __restrict__ stg,
                       float4* out) {
    int i = blockIdx.x * 256 + threadIdx.x;
    if (i < 2 * NN) ((int*)g_cursor)[i] = 0;
    if (i >= 2 * SS * D4) return;
    int row = i >> 6, c = i & 63;
    int side = row >= SS;
    int s = row - side * SS;
    int node = side ? stg[s] : ssr[s];
    size_t src = (size_t)(2 * SS) * D4 + (size_t)side * NN * D4 + (size_t)node * D4 + c;
    out[i] = out[src];
}

// ---------------- launch ----------------
extern "C" void kernel_launch(void* const* d_in, const int* in_sizes, int n_in,
                              void* d_out, int out_size) {
    const float4* fsr = (const float4*)d_in[0];
    const float4* ftg = (const float4*)d_in[1];
    const int2*   esr = (const int2*)d_in[2];
    const int2*   etg = (const int2*)d_in[3];
    const int*    ssr = (const int*)d_in[4];
    const int*    stg = (const int*)d_in[5];
    float4* out = (float4*)d_out;

    k_fill<<<(2 * EE + 255) / 256, 256>>>(esr, etg);
    k_dinv<<<(2 * NN + 255) / 256, 256>>>();
    k_conv<<<(2 * NN * 32 + 255) / 256, 256>>>(fsr, ftg);

    // per-side chain: layer-2 consumes g_h1 while it is still L2-resident;
    // sides sequential keeps the working set under the 126 MB L2
    int lb = NN / 4;   // two warps per node, 4 nodes per 256-thread block
    k_layer<false><<<lb, 256>>>(0, nullptr);
    k_layer<true ><<<lb, 256>>>(0, out);
    k_layer<false><<<lb, 256>>>(1, nullptr);
    k_layer<true ><<<lb, 256>>>(1, out);

    k_seed<<<(2 * SS * D4 + 255) / 256, 256>>>(ssr, stg, out);
}

// round 10
// speedup vs baseline: 1.2484x; 1.2484x over previous
#include <cuda_runtime.h>
#include <cuda_fp16.h>
#include <cstring>

#define NN 100000
#define EE 400000
#define D4 64          // 256 floats = 64 float4 per row
#define SS 10000
#define CAP 64         // bucket capacity per node (Poisson(8): P(>64) ~ 0)

// ---------------- static scratch (no runtime allocation) ----------------
// g_cursor is zero-initialized at module load and re-zeroed at the END of
// each kernel_launch (in k_seed), so every call starts from zeros.
__device__ int    g_cursor[2][NN];            // degree counts (bucket cursors)
__device__ int    g_adj[2][(size_t)NN * CAP]; // bucket adjacency
__device__ float  g_dinv[2][NN];
__device__ uint4  g_h0[2][(size_t)NN * 32];   // fp16 pre-scaled g0 = h*dinv (512B/row)
__device__ uint4  g_h1[2][(size_t)NN * 32];   // fp16 pre-scaled g1

// ---------------- half2 <-> float helpers ----------------
__device__ __forceinline__ float2 u2f(unsigned int u) {
    __half2 h; memcpy(&h, &u, 4); return __half22float2(h);
}
__device__ __forceinline__ unsigned int f2u(float a, float b) {
    __half2 h = __floats2half2_rn(a, b); unsigned int u; memcpy(&u, &h, 4); return u;
}
__device__ __forceinline__ unsigned int hadd2u(unsigned int a, unsigned int b) {
    __half2 x, y; memcpy(&x, &a, 4); memcpy(&y, &b, 4);
    __half2 r = __hadd2(x, y);
    unsigned int u; memcpy(&u, &r, 4); return u;
}
__device__ __forceinline__ uint4 hadd2v(uint4 a, uint4 b) {
    uint4 r;
    r.x = hadd2u(a.x, b.x); r.y = hadd2u(a.y, b.y);
    r.z = hadd2u(a.z, b.z); r.w = hadd2u(a.w, b.w);
    return r;
}
__device__ __forceinline__ void unpack_add8(float* a, uint4 v) {
    float2 f;
    f = u2f(v.x); a[0] += f.x; a[1] += f.y;
    f = u2f(v.y); a[2] += f.x; a[3] += f.y;
    f = u2f(v.z); a[4] += f.x; a[5] += f.y;
    f = u2f(v.w); a[6] += f.x; a[7] += f.y;
}

// ---------------- bucket fill: one pass builds adjacency AND degrees ------
__global__ void k_fill(const int2* __restrict__ esr, const int2* __restrict__ etg) {
    int i = blockIdx.x * 256 + threadIdx.x;
    if (i >= 2 * EE) return;
    int side = i >= EE;
    int j = i - side * EE;
    int2 ab = side ? etg[j] : esr[j];
    int p = atomicAdd(&g_cursor[side][ab.x], 1);
    if (p < CAP) g_adj[side][(size_t)ab.x * CAP + p] = ab.y;
    int q = atomicAdd(&g_cursor[side][ab.y], 1);
    if (q < CAP) g_adj[side][(size_t)ab.y * CAP + q] = ab.x;
}

// dinv[v] = rsqrt(deg[v] + 1)   (cursor count == degree)
__global__ void k_dinv() {
    int i = blockIdx.x * 256 + threadIdx.x;
    if (i >= 2 * NN) return;
    int side = i >= NN;
    int v = i - side * NN;
    g_dinv[side][v] = rsqrtf((float)(g_cursor[side][v] + 1));
}

// g0 = fp16(feats * dinv[row]); one uint4 (8 halfs) per thread
__global__ void k_conv(const float4* __restrict__ fsr, const float4* __restrict__ ftg) {
    int i = blockIdx.x * 256 + threadIdx.x;
    if (i >= 2 * NN * 32) return;
    int side = i >= NN * 32;
    int j = i - side * NN * 32;
    float s = g_dinv[side][j >> 5];
    const float4* f = side ? ftg : fsr;
    float4 x0 = __ldcs(f + 2 * j);        // streaming: feats never reused
    float4 x1 = __ldcs(f + 2 * j + 1);
    uint4 o;
    o.x = f2u(x0.x * s, x0.y * s);
    o.y = f2u(x0.z * s, x0.w * s);
    o.z = f2u(x1.x * s, x1.y * s);
    o.w = f2u(x1.z * s, x1.w * s);
    g_h0[side][j] = o;
}

// ---------------- aggregation: one warp per node, 8 floats / lane --------
// lane l holds float columns [8l .. 8l+7]  (one uint4 = 8 halfs per row)
// The kernel is F2F-convert bound: a 2-level HADD2 tree merges 4 neighbor
// rows in fp16 (full-rate fma pipe), then ONE convert+add into the fp32
// accumulators -- 8 F2F per 4 rows instead of 32.
// FINAL=false: g1[v] = fp16( relu(dinv[v]*acc) * dinv[v] )  -> g_h1
// FINAL=true : row    = l2normalize(dinv[v]*acc)            -> d_out (fp32, stcs)
template <bool FINAL>
__global__ void k_layer(int side, float4* out) {
    int gw = (blockIdx.x * blockDim.x + threadIdx.x) >> 5;
    if (gw >= NN) return;
    int lane = threadIdx.x & 31;

    const uint4* __restrict__ gin = FINAL ? g_h1[side] : g_h0[side];
    float a[8] = {0, 0, 0, 0, 0, 0, 0, 0};
    unpack_add8(a, __ldg(gin + (size_t)gw * 32 + lane));   // self loop (fp32 add)

    int e = min(g_cursor[side][gw], CAP);
    const int* __restrict__ adj = g_adj[side] + (size_t)gw * CAP;
    for (int base = 0; base < e; base += 32) {
        int cnt = min(32, e - base);
        int nb = (lane < cnt) ? __ldg(adj + base + lane) : 0;
        int k = 0;
        for (; k + 4 <= cnt; k += 4) {
            int u0 = __shfl_sync(0xffffffffu, nb, k);
            int u1 = __shfl_sync(0xffffffffu, nb, k + 1);
            uint4 v0 = __ldg(gin + (size_t)u0 * 32 + lane);
            uint4 v1 = __ldg(gin + (size_t)u1 * 32 + lane);
            uint4 p  = hadd2v(v0, v1);                    // frees v0,v1
            int u2 = __shfl_sync(0xffffffffu, nb, k + 2);
            int u3 = __shfl_sync(0xffffffffu, nb, k + 3);
            uint4 v2 = __ldg(gin + (size_t)u2 * 32 + lane);
            uint4 v3 = __ldg(gin + (size_t)u3 * 32 + lane);
            uint4 q  = hadd2v(v2, v3);
            unpack_add8(a, hadd2v(p, q));                 // one convert per 4 rows
        }
        for (; k + 2 <= cnt; k += 2) {                    // pair tail
            int u0 = __shfl_sync(0xffffffffu, nb, k);
            int u1 = __shfl_sync(0xffffffffu, nb, k + 1);
            uint4 v0 = __ldg(gin + (size_t)u0 * 32 + lane);
            uint4 v1 = __ldg(gin + (size_t)u1 * 32 + lane);
            unpack_add8(a, hadd2v(v0, v1));
        }
        if (k < cnt) {                                    // single tail
            int u0 = __shfl_sync(0xffffffffu, nb, k);
            unpack_add8(a, __ldg(gin + (size_t)u0 * 32 + lane));
        }
    }

    float dv = g_dinv[side][gw];
    if (!FINAL) {
        float r[8];
        #pragma unroll
        for (int k = 0; k < 8; k++) r[k] = fmaxf(dv * a[k], 0.f) * dv;
        uint4 o;
        o.x = f2u(r[0], r[1]); o.y = f2u(r[2], r[3]);
        o.z = f2u(r[4], r[5]); o.w = f2u(r[6], r[7]);
        g_h1[side][(size_t)gw * 32 + lane] = o;
    } else {
        float r[8];
        float ss = 0.f;
        #pragma unroll
        for (int k = 0; k < 8; k++) { r[k] = dv * a[k]; ss += r[k] * r[k]; }
        #pragma unroll
        for (int off = 16; off; off >>= 1) ss += __shfl_xor_sync(0xffffffffu, ss, off);
        float inv = 1.0f / fmaxf(sqrtf(ss), 1e-12f);
        float4 r0, r1;
        r0.x = r[0] * inv; r0.y = r[1] * inv; r0.z = r[2] * inv; r0.w = r[3] * inv;
        r1.x = r[4] * inv; r1.y = r[5] * inv; r1.z = r[6] * inv; r1.w = r[7] * inv;
        size_t rb = (size_t)(2 * SS) * D4 + (size_t)side * NN * D4 + (size_t)gw * D4;
        __stcs(out + rb + 2 * lane, r0);       // streaming: keep gather table in L2
        __stcs(out + rb + 2 * lane + 1, r1);
    }
}

// seed gather + re-zero bucket cursors for the next call
__global__ void k_seed(const int* __restrict__ ssr, const int* __restrict__ stg,
                       float4* out) {
    int i = blockIdx.x * 256 + threadIdx.x;
    if (i < 2 * NN) ((int*)g_cursor)[i] = 0;
    if (i >= 2 * SS * D4) return;
    int row = i >> 6, c = i & 63;
    int side = row >= SS;
    int s = row - side * SS;
    int node = side ? stg[s] : ssr[s];
    size_t src = (size_t)(2 * SS) * D4 + (size_t)side * NN * D4 + (size_t)node * D4 + c;
    out[i] = out[src];
}

// ---------------- launch ----------------
extern "C" void kernel_launch(void* const* d_in, const int* in_sizes, int n_in,
                              void* d_out, int out_size) {
    const float4* fsr = (const float4*)d_in[0];
    const float4* ftg = (const float4*)d_in[1];
    const int2*   esr = (const int2*)d_in[2];
    const int2*   etg = (const int2*)d_in[3];
    const int*    ssr = (const int*)d_in[4];
    const int*    stg = (const int*)d_in[5];
    float4* out = (float4*)d_out;

    k_fill<<<(2 * EE + 255) / 256, 256>>>(esr, etg);
    k_dinv<<<(2 * NN + 255) / 256, 256>>>();
    k_conv<<<(2 * NN * 32 + 255) / 256, 256>>>(fsr, ftg);

    // per-side chain: layer-2 consumes g_h1 while it is still L2-resident;
    // sides sequential keeps the working set under the 126 MB L2
    int lb = (NN * 32 + 255) / 256;   // one warp per node
    k_layer<false><<<lb, 256>>>(0, nullptr);
    k_layer<true ><<<lb, 256>>>(0, out);
    k_layer<false><<<lb, 256>>>(1, nullptr);
    k_layer<true ><<<lb, 256>>>(1, out);

    k_seed<<<(2 * SS * D4 + 255) / 256, 256>>>(ssr, stg, out);
}

// round 11
// speedup vs baseline: 1.2956x; 1.0378x over previous
#include <cuda_runtime.h>
#include <cuda_fp16.h>
#include <cstring>

#define NN 100000
#define EE 400000
#define D4 64          // 256 floats = 64 float4 per row
#define SS 10000
#define CAP 64         // bucket capacity per node (Poisson(8): P(>64) ~ 0)

// ---------------- static scratch (no runtime allocation) ----------------
// g_cursor is zero-initialized at module load and re-zeroed at the END of
// each kernel_launch (in k_seed), so every call starts from zeros.
__device__ int    g_cursor[2][NN];            // degree counts (bucket cursors)
__device__ int    g_adj[2][(size_t)NN * CAP]; // bucket adjacency
__device__ float  g_dinv[2][NN];
__device__ uint4  g_h0[2][(size_t)NN * 32];   // fp16 pre-scaled g0 = h*dinv (512B/row)
__device__ uint4  g_h1[2][(size_t)NN * 32];   // fp16 pre-scaled g1

// ---- streams/events for side-parallel execution (created at load time,
// NEVER during capture; record/wait are graph-capturable ops) ----
static cudaStream_t g_sB;
static cudaEvent_t  g_evFork, g_evJoin;
namespace {
struct StreamInit {
    StreamInit() {
        cudaStreamCreateWithFlags(&g_sB, cudaStreamNonBlocking);
        cudaEventCreateWithFlags(&g_evFork, cudaEventDisableTiming);
        cudaEventCreateWithFlags(&g_evJoin, cudaEventDisableTiming);
    }
} g_streamInit;
}

// ---------------- half2 <-> float helpers ----------------
__device__ __forceinline__ float2 u2f(unsigned int u) {
    __half2 h; memcpy(&h, &u, 4); return __half22float2(h);
}
__device__ __forceinline__ unsigned int f2u(float a, float b) {
    __half2 h = __floats2half2_rn(a, b); unsigned int u; memcpy(&u, &h, 4); return u;
}
__device__ __forceinline__ unsigned int hadd2u(unsigned int a, unsigned int b) {
    __half2 x, y; memcpy(&x, &a, 4); memcpy(&y, &b, 4);
    __half2 r = __hadd2(x, y);
    unsigned int u; memcpy(&u, &r, 4); return u;
}
__device__ __forceinline__ uint4 hadd2v(uint4 a, uint4 b) {
    uint4 r;
    r.x = hadd2u(a.x, b.x); r.y = hadd2u(a.y, b.y);
    r.z = hadd2u(a.z, b.z); r.w = hadd2u(a.w, b.w);
    return r;
}
__device__ __forceinline__ void unpack_add8(float* a, uint4 v) {
    float2 f;
    f = u2f(v.x); a[0] += f.x; a[1] += f.y;
    f = u2f(v.y); a[2] += f.x; a[3] += f.y;
    f = u2f(v.z); a[4] += f.x; a[5] += f.y;
    f = u2f(v.w); a[6] += f.x; a[7] += f.y;
}

// ---------------- bucket fill (per side): adjacency AND degrees ----------
__global__ void k_fill(int side, const int2* __restrict__ edges) {
    int j = blockIdx.x * 256 + threadIdx.x;
    if (j >= EE) return;
    int2 ab = edges[j];
    int p = atomicAdd(&g_cursor[side][ab.x], 1);
    if (p < CAP) g_adj[side][(size_t)ab.x * CAP + p] = ab.y;
    int q = atomicAdd(&g_cursor[side][ab.y], 1);
    if (q < CAP) g_adj[side][(size_t)ab.y * CAP + q] = ab.x;
}

// g0 = fp16(feats * dinv[row]) for ONE side; also materializes g_dinv.
// One uint4 (8 halfs) per thread; 8 threads cover one row.
__global__ void k_conv(int side, const float4* __restrict__ f) {
    int j = blockIdx.x * 256 + threadIdx.x;   // uint4 index, < NN*32
    if (j >= NN * 32) return;
    int row = j >> 5;
    float s = rsqrtf((float)(g_cursor[side][row] + 1));
    if ((j & 31) == 0) g_dinv[side][row] = s;  // fused dinv store
    float4 x0 = __ldcs(f + 2 * j);             // streaming: feats never reused
    float4 x1 = __ldcs(f + 2 * j + 1);
    uint4 o;
    o.x = f2u(x0.x * s, x0.y * s);
    o.y = f2u(x0.z * s, x0.w * s);
    o.z = f2u(x1.x * s, x1.y * s);
    o.w = f2u(x1.z * s, x1.w * s);
    g_h0[side][j] = o;
}

// ---------------- aggregation: one warp per node, 8 floats / lane --------
// lane l holds float columns [8l .. 8l+7]  (one uint4 = 8 halfs per row)
// HADD2 tree merges 4 neighbor rows in fp16, then one convert+add to fp32.
// FINAL=false: g1[v] = fp16( relu(dinv[v]*acc) * dinv[v] )  -> g_h1
// FINAL=true : row    = l2normalize(dinv[v]*acc)            -> d_out (fp32, stcs)
template <bool FINAL>
__global__ void k_layer(int side, float4* out) {
    int gw = (blockIdx.x * blockDim.x + threadIdx.x) >> 5;
    if (gw >= NN) return;
    int lane = threadIdx.x & 31;

    const uint4* __restrict__ gin = FINAL ? g_h1[side] : g_h0[side];
    float a[8] = {0, 0, 0, 0, 0, 0, 0, 0};
    unpack_add8(a, __ldg(gin + (size_t)gw * 32 + lane));   // self loop (fp32 add)

    int e = min(g_cursor[side][gw], CAP);
    const int* __restrict__ adj = g_adj[side] + (size_t)gw * CAP;
    for (int base = 0; base < e; base += 32) {
        int cnt = min(32, e - base);
        int nb = (lane < cnt) ? __ldg(adj + base + lane) : 0;
        int k = 0;
        for (; k + 4 <= cnt; k += 4) {
            int u0 = __shfl_sync(0xffffffffu, nb, k);
            int u1 = __shfl_sync(0xffffffffu, nb, k + 1);
            uint4 v0 = __ldg(gin + (size_t)u0 * 32 + lane);
            uint4 v1 = __ldg(gin + (size_t)u1 * 32 + lane);
            uint4 p  = hadd2v(v0, v1);
            int u2 = __shfl_sync(0xffffffffu, nb, k + 2);
            int u3 = __shfl_sync(0xffffffffu, nb, k + 3);
            uint4 v2 = __ldg(gin + (size_t)u2 * 32 + lane);
            uint4 v3 = __ldg(gin + (size_t)u3 * 32 + lane);
            uint4 q  = hadd2v(v2, v3);
            unpack_add8(a, hadd2v(p, q));                 // one convert per 4 rows
        }
        for (; k + 2 <= cnt; k += 2) {                    // pair tail
            int u0 = __shfl_sync(0xffffffffu, nb, k);
            int u1 = __shfl_sync(0xffffffffu, nb, k + 1);
            uint4 v0 = __ldg(gin + (size_t)u0 * 32 + lane);
            uint4 v1 = __ldg(gin + (size_t)u1 * 32 + lane);
            unpack_add8(a, hadd2v(v0, v1));
        }
        if (k < cnt) {                                    // single tail
            int u0 = __shfl_sync(0xffffffffu, nb, k);
            unpack_add8(a, __ldg(gin + (size_t)u0 * 32 + lane));
        }
    }

    float dv = g_dinv[side][gw];
    if (!FINAL) {
        float r[8];
        #pragma unroll
        for (int k = 0; k < 8; k++) r[k] = fmaxf(dv * a[k], 0.f) * dv;
        uint4 o;
        o.x = f2u(r[0], r[1]); o.y = f2u(r[2], r[3]);
        o.z = f2u(r[4], r[5]); o.w = f2u(r[6], r[7]);
        g_h1[side][(size_t)gw * 32 + lane] = o;
    } else {
        float r[8];
        float ss = 0.f;
        #pragma unroll
        for (int k = 0; k < 8; k++) { r[k] = dv * a[k]; ss += r[k] * r[k]; }
        #pragma unroll
        for (int off = 16; off; off >>= 1) ss += __shfl_xor_sync(0xffffffffu, ss, off);
        float inv = 1.0f / fmaxf(sqrtf(ss), 1e-12f);
        float4 r0, r1;
        r0.x = r[0] * inv; r0.y = r[1] * inv; r0.z = r[2] * inv; r0.w = r[3] * inv;
        r1.x = r[4] * inv; r1.y = r[5] * inv; r1.z = r[6] * inv; r1.w = r[7] * inv;
        size_t rb = (size_t)(2 * SS) * D4 + (size_t)side * NN * D4 + (size_t)gw * D4;
        __stcs(out + rb + 2 * lane, r0);       // streaming: keep gather table in L2
        __stcs(out + rb + 2 * lane + 1, r1);
    }
}

// seed gather + re-zero bucket cursors for the next call
__global__ void k_seed(const int* __restrict__ ssr, const int* __restrict__ stg,
                       float4* out) {
    int i = blockIdx.x * 256 + threadIdx.x;
    if (i < 2 * NN) ((int*)g_cursor)[i] = 0;
    if (i >= 2 * SS * D4) return;
    int row = i >> 6, c = i & 63;
    int side = row >= SS;
    int s = row - side * SS;
    int node = side ? stg[s] : ssr[s];
    size_t src = (size_t)(2 * SS) * D4 + (size_t)side * NN * D4 + (size_t)node * D4 + c;
    out[i] = out[src];
}

// ---------------- launch ----------------
extern "C" void kernel_launch(void* const* d_in, const int* in_sizes, int n_in,
                              void* d_out, int out_size) {
    const float4* fsr = (const float4*)d_in[0];
    const float4* ftg = (const float4*)d_in[1];
    const int2*   esr = (const int2*)d_in[2];
    const int2*   etg = (const int2*)d_in[3];
    const int*    ssr = (const int*)d_in[4];
    const int*    stg = (const int*)d_in[5];
    float4* out = (float4*)d_out;

    int fb = (EE + 255) / 256;
    int cb = (NN * 32 + 255) / 256;
    int lb = (NN * 32 + 255) / 256;   // one warp per node

    // fork: side-1 chain runs on g_sB, overlapping side-0's chain
    cudaEventRecord(g_evFork, 0);
    cudaStreamWaitEvent(g_sB, g_evFork, 0);

    // side 0 on the main (capture) stream
    k_fill <<<fb, 256>>>(0, esr);
    k_conv <<<cb, 256>>>(0, fsr);
    k_layer<false><<<lb, 256>>>(0, nullptr);
    k_layer<true ><<<lb, 256>>>(0, out);

    // side 1 on the side stream
    k_fill <<<fb, 256, 0, g_sB>>>(1, etg);
    k_conv <<<cb, 256, 0, g_sB>>>(1, ftg);
    k_layer<false><<<lb, 256, 0, g_sB>>>(1, nullptr);
    k_layer<true ><<<lb, 256, 0, g_sB>>>(1, out);

    // join, then seed gather (+ cursor re-zero) on the main stream
    cudaEventRecord(g_evJoin, g_sB);
    cudaStreamWaitEvent(0, g_evJoin, 0);
    k_seed<<<(2 * SS * D4 + 255) / 256, 256>>>(ssr, stg, out);
}

// round 12
// speedup vs baseline: 1.3402x; 1.0344x over previous
#include <cuda_runtime.h>
#include <cuda_fp16.h>
#include <cstring>

#define NN 100000
#define EE 400000
#define D4 64          // 256 floats = 64 float4 per row
#define SS 10000
#define CAP 64         // bucket capacity per node (Poisson(8): P(>64) ~ 0)

// ---------------- static scratch (no runtime allocation) ----------------
// g_cursor is zero-initialized at module load and re-zeroed at the END of
// each kernel_launch (in k_seed, per side), so every call starts from zeros.
__device__ int    g_cursor[2][NN];            // degree counts (bucket cursors)
__device__ int    g_adj[2][(size_t)NN * CAP]; // bucket adjacency
__device__ float  g_dinv[2][NN];
__device__ uint4  g_h0[2][(size_t)NN * 32];   // fp16 pre-scaled g0 = h*dinv (512B/row)
__device__ uint4  g_h1[2][(size_t)NN * 32];   // fp16 pre-scaled g1

// ---- streams/events for side-parallel execution (created at load time,
// NEVER during capture; record/wait are graph-capturable ops) ----
static cudaStream_t g_sB;
static cudaEvent_t  g_evFork, g_evConv0, g_evJoin;
namespace {
struct StreamInit {
    StreamInit() {
        cudaStreamCreateWithFlags(&g_sB, cudaStreamNonBlocking);
        cudaEventCreateWithFlags(&g_evFork,  cudaEventDisableTiming);
        cudaEventCreateWithFlags(&g_evConv0, cudaEventDisableTiming);
        cudaEventCreateWithFlags(&g_evJoin,  cudaEventDisableTiming);
    }
} g_streamInit;
}

// ---------------- half2 <-> float helpers ----------------
__device__ __forceinline__ float2 u2f(unsigned int u) {
    __half2 h; memcpy(&h, &u, 4); return __half22float2(h);
}
__device__ __forceinline__ unsigned int f2u(float a, float b) {
    __half2 h = __floats2half2_rn(a, b); unsigned int u; memcpy(&u, &h, 4); return u;
}
__device__ __forceinline__ unsigned int hadd2u(unsigned int a, unsigned int b) {
    __half2 x, y; memcpy(&x, &a, 4); memcpy(&y, &b, 4);
    __half2 r = __hadd2(x, y);
    unsigned int u; memcpy(&u, &r, 4); return u;
}
__device__ __forceinline__ uint4 hadd2v(uint4 a, uint4 b) {
    uint4 r;
    r.x = hadd2u(a.x, b.x); r.y = hadd2u(a.y, b.y);
    r.z = hadd2u(a.z, b.z); r.w = hadd2u(a.w, b.w);
    return r;
}
__device__ __forceinline__ void unpack_add8(float* a, uint4 v) {
    float2 f;
    f = u2f(v.x); a[0] += f.x; a[1] += f.y;
    f = u2f(v.y); a[2] += f.x; a[3] += f.y;
    f = u2f(v.z); a[4] += f.x; a[5] += f.y;
    f = u2f(v.w); a[6] += f.x; a[7] += f.y;
}

// ---------------- bucket fill (per side): 2 edges / thread --------------
__global__ void k_fill(int side, const int4* __restrict__ edges2) {
    int i = blockIdx.x * 256 + threadIdx.x;
    if (i >= EE / 2) return;
    int4 e = edges2[i];                       // edges (e.x,e.y) and (e.z,e.w)
    int p = atomicAdd(&g_cursor[side][e.x], 1);   // 4 independent atomics
    int q = atomicAdd(&g_cursor[side][e.y], 1);   // in flight (MLP=4)
    int r = atomicAdd(&g_cursor[side][e.z], 1);
    int s = atomicAdd(&g_cursor[side][e.w], 1);
    if (p < CAP) g_adj[side][(size_t)e.x * CAP + p] = e.y;
    if (q < CAP) g_adj[side][(size_t)e.y * CAP + q] = e.x;
    if (r < CAP) g_adj[side][(size_t)e.z * CAP + r] = e.w;
    if (s < CAP) g_adj[side][(size_t)e.w * CAP + s] = e.z;
}

// g0 = fp16(feats * dinv[row]) for ONE side; also materializes g_dinv.
__global__ void k_conv(int side, const float4* __restrict__ f) {
    int j = blockIdx.x * 256 + threadIdx.x;   // uint4 index, < NN*32
    if (j >= NN * 32) return;
    int row = j >> 5;
    float s = rsqrtf((float)(g_cursor[side][row] + 1));
    if ((j & 31) == 0) g_dinv[side][row] = s;  // fused dinv store
    float4 x0 = __ldcs(f + 2 * j);             // streaming: feats never reused
    float4 x1 = __ldcs(f + 2 * j + 1);
    uint4 o;
    o.x = f2u(x0.x * s, x0.y * s);
    o.y = f2u(x0.z * s, x0.w * s);
    o.z = f2u(x1.x * s, x1.y * s);
    o.w = f2u(x1.z * s, x1.w * s);
    g_h0[side][j] = o;
}

// ---------------- aggregation: one warp per node, 8 floats / lane --------
// lane l holds float columns [8l .. 8l+7]  (one uint4 = 8 halfs per row)
// HADD2 tree merges 4 neighbor rows in fp16, then one convert+add to fp32.
// FINAL=false: g1[v] = fp16( relu(dinv[v]*acc) * dinv[v] )  -> g_h1
// FINAL=true : row    = l2normalize(dinv[v]*acc)            -> d_out (fp32, stcs)
template <bool FINAL>
__global__ void k_layer(int side, float4* out) {
    int gw = (blockIdx.x * blockDim.x + threadIdx.x) >> 5;
    if (gw >= NN) return;
    int lane = threadIdx.x & 31;

    const uint4* __restrict__ gin = FINAL ? g_h1[side] : g_h0[side];
    float a[8] = {0, 0, 0, 0, 0, 0, 0, 0};
    unpack_add8(a, __ldg(gin + (size_t)gw * 32 + lane));   // self loop (fp32 add)

    int e = min(g_cursor[side][gw], CAP);
    const int* __restrict__ adj = g_adj[side] + (size_t)gw * CAP;
    for (int base = 0; base < e; base += 32) {
        int cnt = min(32, e - base);
        int nb = (lane < cnt) ? __ldg(adj + base + lane) : 0;
        int k = 0;
        for (; k + 4 <= cnt; k += 4) {
            int u0 = __shfl_sync(0xffffffffu, nb, k);
            int u1 = __shfl_sync(0xffffffffu, nb, k + 1);
            uint4 v0 = __ldg(gin + (size_t)u0 * 32 + lane);
            uint4 v1 = __ldg(gin + (size_t)u1 * 32 + lane);
            uint4 p  = hadd2v(v0, v1);
            int u2 = __shfl_sync(0xffffffffu, nb, k + 2);
            int u3 = __shfl_sync(0xffffffffu, nb, k + 3);
            uint4 v2 = __ldg(gin + (size_t)u2 * 32 + lane);
            uint4 v3 = __ldg(gin + (size_t)u3 * 32 + lane);
            uint4 q  = hadd2v(v2, v3);
            unpack_add8(a, hadd2v(p, q));                 // one convert per 4 rows
        }
        for (; k + 2 <= cnt; k += 2) {                    // pair tail
            int u0 = __shfl_sync(0xffffffffu, nb, k);
            int u1 = __shfl_sync(0xffffffffu, nb, k + 1);
            uint4 v0 = __ldg(gin + (size_t)u0 * 32 + lane);
            uint4 v1 = __ldg(gin + (size_t)u1 * 32 + lane);
            unpack_add8(a, hadd2v(v0, v1));
        }
        if (k < cnt) {                                    // single tail
            int u0 = __shfl_sync(0xffffffffu, nb, k);
            unpack_add8(a, __ldg(gin + (size_t)u0 * 32 + lane));
        }
    }

    float dv = g_dinv[side][gw];
    if (!FINAL) {
        float r[8];
        #pragma unroll
        for (int k = 0; k < 8; k++) r[k] = fmaxf(dv * a[k], 0.f) * dv;
        uint4 o;
        o.x = f2u(r[0], r[1]); o.y = f2u(r[2], r[3]);
        o.z = f2u(r[4], r[5]); o.w = f2u(r[6], r[7]);
        g_h1[side][(size_t)gw * 32 + lane] = o;
    } else {
        float r[8];
        float ss = 0.f;
        #pragma unroll
        for (int k = 0; k < 8; k++) { r[k] = dv * a[k]; ss += r[k] * r[k]; }
        #pragma unroll
        for (int off = 16; off; off >>= 1) ss += __shfl_xor_sync(0xffffffffu, ss, off);
        float inv = 1.0f / fmaxf(sqrtf(ss), 1e-12f);
        float4 r0, r1;
        r0.x = r[0] * inv; r0.y = r[1] * inv; r0.z = r[2] * inv; r0.w = r[3] * inv;
        r1.x = r[4] * inv; r1.y = r[5] * inv; r1.z = r[6] * inv; r1.w = r[7] * inv;
        size_t rb = (size_t)(2 * SS) * D4 + (size_t)side * NN * D4 + (size_t)gw * D4;
        __stcs(out + rb + 2 * lane, r0);       // streaming: keep gather table in L2
        __stcs(out + rb + 2 * lane + 1, r1);
    }
}

// per-side seed gather + re-zero that side's bucket cursors
__global__ void k_seed(int side, const int* __restrict__ seeds, float4* out) {
    int i = blockIdx.x * 256 + threadIdx.x;   // < SS*D4 = 640000; NN < that
    if (i < NN) g_cursor[side][i] = 0;
    if (i >= SS * D4) return;
    int row = i >> 6, c = i & 63;
    int node = seeds[row];
    size_t src = (size_t)(2 * SS) * D4 + (size_t)side * NN * D4 + (size_t)node * D4 + c;
    out[(size_t)side * SS * D4 + i] = out[src];
}

// ---------------- launch ----------------
extern "C" void kernel_launch(void* const* d_in, const int* in_sizes, int n_in,
                              void* d_out, int out_size) {
    const float4* fsr = (const float4*)d_in[0];
    const float4* ftg = (const float4*)d_in[1];
    const int4*   esr = (const int4*)d_in[2];
    const int4*   etg = (const int4*)d_in[3];
    const int*    ssr = (const int*)d_in[4];
    const int*    stg = (const int*)d_in[5];
    float4* out = (float4*)d_out;

    int fb = (EE / 2 + 255) / 256;
    int cb = (NN * 32 + 255) / 256;
    int lb = (NN * 32 + 255) / 256;   // one warp per node
    int sb = (SS * D4 + 255) / 256;

    cudaEventRecord(g_evFork, 0);
    cudaStreamWaitEvent(g_sB, g_evFork, 0);

    // side 0 on the main (capture) stream
    k_fill<<<fb, 256>>>(0, esr);
    k_conv<<<cb, 256>>>(0, fsr);
    cudaEventRecord(g_evConv0, 0);            // gate for conv1 (DRAM-wall skew)
    k_layer<false><<<lb, 256>>>(0, nullptr);
    k_layer<true ><<<lb, 256>>>(0, out);
    k_seed<<<sb, 256>>>(0, ssr, out);         // hides under side-1 layers

    // side 1: fill early; conv1 waits for conv0 so its DRAM traffic overlaps
    // side-0's L2-resident layer kernels instead of colliding with conv0
    k_fill<<<fb, 256, 0, g_sB>>>(1, etg);
    cudaStreamWaitEvent(g_sB, g_evConv0, 0);
    k_conv<<<cb, 256, 0, g_sB>>>(1, ftg);
    k_layer<false><<<lb, 256, 0, g_sB>>>(1, nullptr);
    k_layer<true ><<<lb, 256, 0, g_sB>>>(1, out);
    k_seed<<<sb, 256, 0, g_sB>>>(1, stg, out);

    // join side stream back into the main stream
    cudaEventRecord(g_evJoin, g_sB);
    cudaStreamWaitEvent(0, g_evJoin, 0);
}